// round 6
// baseline (speedup 1.0000x reference)
#include <cuda_runtime.h>
#include <cuda_fp16.h>
#include <cstdint>

#define B_DIM 512
#define T_DIM 128
#define D_DIM 300
#define DPAD  320
#define H_DIM 1024

typedef uint32_t u32;

// ------------------------------------------------------------------
// Persistent device buffers (static globals; no runtime allocation)
// ------------------------------------------------------------------
__device__ __align__(16) __half g_x[(size_t)B_DIM * T_DIM * DPAD];
__device__ __align__(16) __half g_wih0[(size_t)4 * H_DIM * DPAD];
__device__ __align__(16) __half g_whh0[(size_t)4 * H_DIM * H_DIM];
__device__ __align__(16) __half g_wih1[(size_t)4 * H_DIM * H_DIM];
__device__ __align__(16) __half g_whh1[(size_t)4 * H_DIM * H_DIM];
__device__ __align__(16) __half g_h0b[2][(size_t)B_DIM * H_DIM];
__device__ __align__(16) __half g_h1b[2][(size_t)B_DIM * H_DIM];
__device__ __align__(16) float g_c0[(size_t)B_DIM * H_DIM];
__device__ __align__(16) float g_c1[(size_t)B_DIM * H_DIM];
__device__ __align__(16) float g_acc[(size_t)B_DIM * H_DIM];

// ------------------------------------------------------------------
// Helpers (sm_80-compatible: cp.async / ldmatrix / mma.sync)
// ------------------------------------------------------------------
__device__ __forceinline__ u32 smem_to_u32(const void* p) {
    u32 a;
    asm("{ .reg .u64 t; cvta.to.shared.u64 t, %1; cvt.u32.u64 %0, t; }" : "=r"(a) : "l"(p));
    return a;
}
__device__ __forceinline__ void cp16(u32 s, const void* g) {
    asm volatile("cp.async.cg.shared.global [%0], [%1], 16;" :: "r"(s), "l"(g));
}
#define CP_COMMIT() asm volatile("cp.async.commit_group;" ::: "memory")
#define CP_WAIT1()  asm volatile("cp.async.wait_group 1;" ::: "memory")
#define CP_WAIT0()  asm volatile("cp.async.wait_group 0;" ::: "memory")

__device__ __forceinline__ void ldsm4(u32 addr, u32* r) {
    asm volatile("ldmatrix.sync.aligned.m8n8.x4.shared.b16 {%0,%1,%2,%3}, [%4];"
                 : "=r"(r[0]), "=r"(r[1]), "=r"(r[2]), "=r"(r[3]) : "r"(addr));
}
__device__ __forceinline__ void mma_f16(float* d, const u32* a, u32 b0, u32 b1) {
    asm volatile("mma.sync.aligned.m16n8k16.row.col.f32.f16.f16.f32 "
                 "{%0,%1,%2,%3}, {%4,%5,%6,%7}, {%8,%9}, {%0,%1,%2,%3};"
                 : "+f"(d[0]), "+f"(d[1]), "+f"(d[2]), "+f"(d[3])
                 : "r"(a[0]), "r"(a[1]), "r"(a[2]), "r"(a[3]), "r"(b0), "r"(b1));
}

// SMEM tile: [128 rows][64 fp16] = 128B/row = 8 x 16B chunks; swizzle q^(row&7)
__device__ __forceinline__ u32 swz(u32 row, u32 q) {
    return row * 128u + ((q ^ (row & 7u)) << 4);
}

__device__ __forceinline__ float sigf(float x) { return __fdividef(1.0f, 1.0f + __expf(-x)); }
__device__ __forceinline__ float tanhf_(float x) {
    return 1.0f - 2.0f * __fdividef(1.0f, 1.0f + __expf(2.0f * x));
}

#define TILE_B   16384          // 128 x 64 fp16
#define BUF_B    (2 * TILE_B)   // A, W
#define N_STAGE  3
#define SMEM_TOT (1024 + N_STAGE * BUF_B)  // 99328

// ------------------------------------------------------------------
// Fused GEMM + LSTM-cell step kernel (one job = one 128x128 tile).
// CTA: 128 threads = 4 warps (2 M x 2 N), warp tile 64x64, BK=64.
// mode 0: grid 128, all layer0 @ step t
// mode 1: grid 256, blocks [0,128): layer1 @ t; [128,256): layer0 @ t+1
// mode 2: grid 128, all layer1 @ step t
// gates col n -> W row (n&3)*H + u0 + (n>>2)  (gate-interleaved N)
// ------------------------------------------------------------------
__global__ void __launch_bounds__(128, 2)
lstm_step(int mode, int t,
          const float* __restrict__ bih0, const float* __restrict__ bhh0,
          const float* __restrict__ bih1, const float* __restrict__ bhh1) {
    extern __shared__ __align__(16) char smem[];
    const u32 sb = smem_to_u32(smem) + 1024;
    const int tid = threadIdx.x;
    const int lane = tid & 31;
    const int wid = tid >> 5;
    const int wm = wid >> 1;          // 0..1 -> 64 rows
    const int wn = wid & 1;           // 0..1 -> 64 cols

    int jb = blockIdx.x;
    int layer, step;
    if (mode == 0)      { layer = 0; step = t; }
    else if (mode == 2) { layer = 1; step = t; }
    else {
        if (jb < 128) { layer = 1; step = t; }
        else          { layer = 0; step = t + 1; jb -= 128; }
    }
    const int pp = step & 1;
    const int u0 = (jb & 31) * 32;    // unit tile
    const int m0 = (jb >> 5) * 128;   // batch tile

    const float* bih = layer ? bih1 : bih0;
    const float* bhh = layer ? bhh1 : bhh0;

    float* sbias = (float*)smem;      // [128]
    {
        const int wr = (tid & 3) * H_DIM + u0 + (tid >> 2);
        sbias[tid] = bih[wr] + bhh[wr];
    }

    // loader: thread tid owns row tid of both tiles (A: batch, W: gate-col)
    const int r = tid;
    const int wrow = (r & 3) * H_DIM + u0 + (r >> 2);

    const __half *Ar[2], *Wr[2];
    int nc0;
    if (layer == 0) {
        Ar[0] = g_x + (size_t)(m0 + r) * (T_DIM * DPAD) + (size_t)step * DPAD;
        Wr[0] = g_wih0 + (size_t)wrow * DPAD;
        nc0 = DPAD / 64;  // 5
        Ar[1] = g_h0b[pp] + (size_t)(m0 + r) * H_DIM;
        Wr[1] = g_whh0 + (size_t)wrow * H_DIM;
    } else {
        Ar[0] = g_h0b[pp ^ 1] + (size_t)(m0 + r) * H_DIM;  // h0 of this step
        Wr[0] = g_wih1 + (size_t)wrow * H_DIM;
        nc0 = H_DIM / 64;  // 16
        Ar[1] = g_h1b[pp] + (size_t)(m0 + r) * H_DIM;
        Wr[1] = g_whh1 + (size_t)wrow * H_DIM;
    }
    const int NC = nc0 + H_DIM / 64;  // 21 or 32

    float acc[4][8][4];
#pragma unroll
    for (int mi = 0; mi < 4; mi++)
#pragma unroll
        for (int nf = 0; nf < 8; nf++)
#pragma unroll
            for (int q = 0; q < 4; q++) acc[mi][nf][q] = 0.0f;

    auto ldchunk = [&](int c, int buf) {
        const int sg = (c < nc0) ? 0 : 1;
        const int k0 = ((c < nc0) ? c : (c - nc0)) * 64;
        const __half* pa = Ar[sg];
        const __half* pw = Wr[sg];
        const u32 d = sb + (u32)buf * BUF_B;
#pragma unroll
        for (int q = 0; q < 8; q++) {
            const u32 so = swz((u32)r, (u32)q);
            const int e = k0 + q * 8;
            cp16(d + so, pa + e);
            cp16(d + TILE_B + so, pw + e);
        }
    };

    ldchunk(0, 0); CP_COMMIT();
    ldchunk(1, 1); CP_COMMIT();

    int buf = 0, nbuf = 2;  // buffer of chunk c; buffer for chunk c+2
    for (int c = 0; c < NC; c++) {
        if (c + 1 < NC) { CP_WAIT1(); }
        else            { CP_WAIT0(); }
        __syncthreads();  // chunk c visible to all; prior reads of nbuf done
        if (c + 2 < NC) { ldchunk(c + 2, nbuf); CP_COMMIT(); }

        const u32 bA = sb + (u32)buf * BUF_B;
        const u32 bW = bA + TILE_B;

#pragma unroll
        for (int kk = 0; kk < 4; kk++) {
            u32 a[4][4], w[4][4];
            const u32 aq = 2 * kk + (lane >> 4);
#pragma unroll
            for (int mi = 0; mi < 4; mi++) {
                const u32 row = wm * 64 + mi * 16 + (lane & 15);
                ldsm4(bA + swz(row, aq), a[mi]);
            }
            const u32 wq = 2 * kk + ((lane >> 3) & 1);
#pragma unroll
            for (int nf2 = 0; nf2 < 4; nf2++) {
                const u32 row = wn * 64 + nf2 * 16 + (lane & 7) + ((lane >> 4) << 3);
                ldsm4(bW + swz(row, wq), w[nf2]);
            }
#pragma unroll
            for (int mi = 0; mi < 4; mi++)
#pragma unroll
                for (int nf = 0; nf < 8; nf++) {
                    const u32* W = w[nf >> 1] + (nf & 1) * 2;
                    mma_f16(acc[mi][nf], a[mi], W[0], W[1]);
                }
        }
        buf = (buf + 1 == N_STAGE) ? 0 : buf + 1;
        nbuf = (nbuf + 1 == N_STAGE) ? 0 : nbuf + 1;
    }

    // ---------------- fused LSTM epilogue ----------------
    float* cmem = layer ? g_c1 : g_c0;
    __half* hout = (layer ? g_h1b[pp ^ 1] : g_h0b[pp ^ 1]);
    const bool owner = ((lane & 1) == 0);
    const int cc = 2 * (lane & 3);

#pragma unroll
    for (int mi = 0; mi < 4; mi++)
#pragma unroll
        for (int nf = 0; nf < 8; nf++) {
            float v0 = acc[mi][nf][0], v1 = acc[mi][nf][1];
            float v2 = acc[mi][nf][2], v3 = acc[mi][nf][3];
            const float p0 = __shfl_xor_sync(0xffffffffu, v0, 1);
            const float p1 = __shfl_xor_sync(0xffffffffu, v1, 1);
            const float p2 = __shfl_xor_sync(0xffffffffu, v2, 1);
            const float p3 = __shfl_xor_sync(0xffffffffu, v3, 1);
            if (owner) {
                const int nl = wn * 64 + nf * 8 + cc;
                const int ucol = u0 + (nl >> 2);
                const float bi = sbias[nl], bf = sbias[nl + 1];
                const float bg = sbias[nl + 2], bo = sbias[nl + 3];
                const int rowa = m0 + wm * 64 + mi * 16 + (lane >> 2);
#pragma unroll
                for (int rh = 0; rh < 2; rh++) {
                    const int b = rowa + rh * 8;
                    const float iv = (rh ? v2 : v0) + bi;
                    const float fv = (rh ? v3 : v1) + bf;
                    const float gv = (rh ? p2 : p0) + bg;
                    const float ov = (rh ? p3 : p1) + bo;
                    const size_t ci = (size_t)b * H_DIM + ucol;
                    const float cold = cmem[ci];
                    const float cn = sigf(fv) * cold + sigf(iv) * tanhf_(gv);
                    const float hn = sigf(ov) * tanhf_(cn);
                    cmem[ci] = cn;
                    hout[ci] = __float2half(hn);
                    if (layer) g_acc[ci] += hn;
                }
            }
        }
}

// ------------------------------------------------------------------
// Single fused prologue: convert weights/x to fp16, zero states.
// ------------------------------------------------------------------
__global__ void prolog_k(const float* __restrict__ x,
                         const float* __restrict__ Wih0, const float* __restrict__ Whh0,
                         const float* __restrict__ Wih1, const float* __restrict__ Whh1) {
    const size_t stride = (size_t)gridDim.x * blockDim.x;
    const size_t tid0 = (size_t)blockIdx.x * blockDim.x + threadIdx.x;

    // Wih0: [4H, DPAD] padded from [4H, D]
    {
        const size_t n = (size_t)4 * H_DIM * DPAD;
        for (size_t i = tid0; i < n; i += stride) {
            const size_t row = i / DPAD;
            const int k = (int)(i % DPAD);
            g_wih0[i] = __float2half((k < D_DIM) ? Wih0[row * D_DIM + k] : 0.0f);
        }
    }
    // Whh0, Wih1, Whh1: [4H, H]
    {
        const size_t n = (size_t)4 * H_DIM * H_DIM;
        for (size_t i = tid0; i < n; i += stride) {
            g_whh0[i] = __float2half(Whh0[i]);
            g_wih1[i] = __float2half(Wih1[i]);
            g_whh1[i] = __float2half(Whh1[i]);
        }
    }
    // x: [B*T, DPAD] padded from [B*T, D]
    {
        const size_t n = (size_t)B_DIM * T_DIM * DPAD;
        for (size_t i = tid0; i < n; i += stride) {
            const size_t bt = i / DPAD;
            const int k = (int)(i % DPAD);
            g_x[i] = __float2half((k < D_DIM) ? x[bt * D_DIM + k] : 0.0f);
        }
    }
    // states
    {
        const size_t n = (size_t)B_DIM * H_DIM;
        for (size_t i = tid0; i < n; i += stride) {
            g_h0b[0][i] = __float2half(0.0f);
            g_h1b[0][i] = __float2half(0.0f);
            g_c0[i] = 0.0f; g_c1[i] = 0.0f; g_acc[i] = 0.0f;
        }
    }
}

__global__ void finalize_k(const float* __restrict__ Wdec,
                           const float* __restrict__ bdec, float* __restrict__ out) {
    const int b = blockIdx.x;
    const int tid = threadIdx.x;  // 128
    float p = 0.0f;
    for (int u = tid; u < H_DIM; u += 128)
        p += g_acc[(size_t)b * H_DIM + u] * Wdec[u];
#pragma unroll
    for (int o = 16; o; o >>= 1) p += __shfl_down_sync(0xffffffffu, p, o);
    __shared__ float red[4];
    if ((tid & 31) == 0) red[tid >> 5] = p;
    __syncthreads();
    if (tid == 0)
        out[b] = (red[0] + red[1] + red[2] + red[3]) * (1.0f / (float)T_DIM) + bdec[0];
}

// ------------------------------------------------------------------
extern "C" void kernel_launch(void* const* d_in, const int* in_sizes, int n_in,
                              void* d_out, int out_size) {
    const float* x    = (const float*)d_in[0];
    const float* Wih0 = (const float*)d_in[1];
    const float* Whh0 = (const float*)d_in[2];
    const float* bih0 = (const float*)d_in[3];
    const float* bhh0 = (const float*)d_in[4];
    const float* Wih1 = (const float*)d_in[5];
    const float* Whh1 = (const float*)d_in[6];
    const float* bih1 = (const float*)d_in[7];
    const float* bhh1 = (const float*)d_in[8];
    const float* Wdec = (const float*)d_in[9];
    const float* bdec = (const float*)d_in[10];
    float* out = (float*)d_out;

    cudaFuncSetAttribute(lstm_step, cudaFuncAttributeMaxDynamicSharedMemorySize, SMEM_TOT);

    prolog_k<<<2048, 256>>>(x, Wih0, Whh0, Wih1, Whh1);

    // step 0 layer0 alone
    lstm_step<<<128, 128, SMEM_TOT>>>(0, 0, bih0, bhh0, bih1, bhh1);
    // merged intervals: layer1[t] || layer0[t+1]
    for (int t = 0; t < T_DIM - 1; ++t)
        lstm_step<<<256, 128, SMEM_TOT>>>(1, t, bih0, bhh0, bih1, bhh1);
    // final layer1
    lstm_step<<<128, 128, SMEM_TOT>>>(2, T_DIM - 1, bih0, bhh0, bih1, bhh1);

    finalize_k<<<B_DIM, 128>>>(Wdec, bdec, out);
}

// round 7
// speedup vs baseline: 1.4736x; 1.4736x over previous
#include <cuda_runtime.h>
#include <cuda_fp16.h>
#include <cstdint>

#define B_DIM 512
#define T_DIM 128
#define D_DIM 300
#define DPAD  320
#define H_DIM 1024

typedef uint32_t u32;

// ------------------------------------------------------------------
// Persistent device buffers (static globals; no runtime allocation)
// ------------------------------------------------------------------
__device__ __align__(16) __half g_x[(size_t)B_DIM * T_DIM * DPAD];
__device__ __align__(16) __half g_wih0[(size_t)4 * H_DIM * DPAD];
__device__ __align__(16) __half g_whh0[(size_t)4 * H_DIM * H_DIM];
__device__ __align__(16) __half g_wih1[(size_t)4 * H_DIM * H_DIM];
__device__ __align__(16) __half g_whh1[(size_t)4 * H_DIM * H_DIM];
__device__ __align__(16) __half g_h0b[2][(size_t)B_DIM * H_DIM];
__device__ __align__(16) __half g_h1b[2][(size_t)B_DIM * H_DIM];
__device__ __align__(16) float g_c0[(size_t)B_DIM * H_DIM];
__device__ __align__(16) float g_c1[(size_t)B_DIM * H_DIM];
__device__ __align__(16) float g_acc[(size_t)B_DIM * H_DIM];

// ------------------------------------------------------------------
// Helpers (sm_80-compatible: cp.async / ldmatrix / mma.sync)
// ------------------------------------------------------------------
__device__ __forceinline__ u32 smem_to_u32(const void* p) {
    u32 a;
    asm("{ .reg .u64 t; cvta.to.shared.u64 t, %1; cvt.u32.u64 %0, t; }" : "=r"(a) : "l"(p));
    return a;
}
__device__ __forceinline__ void cp16(u32 s, const void* g) {
    asm volatile("cp.async.cg.shared.global [%0], [%1], 16;" :: "r"(s), "l"(g));
}
#define CP_COMMIT() asm volatile("cp.async.commit_group;" ::: "memory")
#define CP_WAIT1()  asm volatile("cp.async.wait_group 1;" ::: "memory")
#define CP_WAIT0()  asm volatile("cp.async.wait_group 0;" ::: "memory")

__device__ __forceinline__ void ldsm4(u32 addr, u32* r) {
    asm volatile("ldmatrix.sync.aligned.m8n8.x4.shared.b16 {%0,%1,%2,%3}, [%4];"
                 : "=r"(r[0]), "=r"(r[1]), "=r"(r[2]), "=r"(r[3]) : "r"(addr));
}
__device__ __forceinline__ void mma_f16(float* d, const u32* a, u32 b0, u32 b1) {
    asm volatile("mma.sync.aligned.m16n8k16.row.col.f32.f16.f16.f32 "
                 "{%0,%1,%2,%3}, {%4,%5,%6,%7}, {%8,%9}, {%0,%1,%2,%3};"
                 : "+f"(d[0]), "+f"(d[1]), "+f"(d[2]), "+f"(d[3])
                 : "r"(a[0]), "r"(a[1]), "r"(a[2]), "r"(a[3]), "r"(b0), "r"(b1));
}

// SMEM tile: [128 rows][64 fp16] = 128B/row = 8 x 16B chunks; swizzle q^(row&7)
__device__ __forceinline__ u32 swz(u32 row, u32 q) {
    return row * 128u + ((q ^ (row & 7u)) << 4);
}

__device__ __forceinline__ float sigf(float x) { return __fdividef(1.0f, 1.0f + __expf(-x)); }
__device__ __forceinline__ float tanhf_(float x) {
    return 1.0f - 2.0f * __fdividef(1.0f, 1.0f + __expf(2.0f * x));
}

#define TILE_B   16384          // 128 x 64 fp16
#define BUF_B    (2 * TILE_B)   // A, W
#define N_STAGE  3
#define SMEM_TOT (1024 + N_STAGE * BUF_B)  // 99328 -> 2 CTAs/SM

// ------------------------------------------------------------------
// Fused GEMM + LSTM-cell step kernel (one job = one 128x128 tile).
// CTA: 256 threads = 8 warps (2 M x 4 N), warp tile 64x32, BK=64.
// mode 0: grid 128, all layer0 @ step t
// mode 1: grid 256, blocks [0,128): layer1 @ t; [128,256): layer0 @ t+1
// mode 2: grid 128, all layer1 @ step t
// gates col n -> W row (n&3)*H + u0 + (n>>2)  (gate-interleaved N)
// ------------------------------------------------------------------
__global__ void __launch_bounds__(256, 2)
lstm_step(int mode, int t,
          const float* __restrict__ bih0, const float* __restrict__ bhh0,
          const float* __restrict__ bih1, const float* __restrict__ bhh1) {
    extern __shared__ __align__(16) char smem[];
    const u32 sb = smem_to_u32(smem) + 1024;
    const int tid = threadIdx.x;
    const int lane = tid & 31;
    const int wid = tid >> 5;
    const int wm = wid >> 2;          // 0..1 -> 64 rows
    const int wn = wid & 3;           // 0..3 -> 32 cols

    int jb = blockIdx.x;
    int layer, step;
    if (mode == 0)      { layer = 0; step = t; }
    else if (mode == 2) { layer = 1; step = t; }
    else {
        if (jb < 128) { layer = 1; step = t; }
        else          { layer = 0; step = t + 1; jb -= 128; }
    }
    const int pp = step & 1;
    const int u0 = (jb & 31) * 32;    // unit tile
    const int m0 = (jb >> 5) * 128;   // batch tile

    const float* bih = layer ? bih1 : bih0;
    const float* bhh = layer ? bhh1 : bhh0;

    float* sbias = (float*)smem;      // [128]
    if (tid < 128) {
        const int wr = (tid & 3) * H_DIM + u0 + (tid >> 2);
        sbias[tid] = bih[wr] + bhh[wr];
    }

    // loader assignment: row r (0..127), chunk block h4 (0..3 or 4..7)
    const int r  = tid >> 1;
    const int h4 = (tid & 1) * 4;
    const int wrow = (r & 3) * H_DIM + u0 + (r >> 2);

    const __half *Ar[2], *Wr[2];
    int nc0;
    if (layer == 0) {
        Ar[0] = g_x + (size_t)(m0 + r) * (T_DIM * DPAD) + (size_t)step * DPAD;
        Wr[0] = g_wih0 + (size_t)wrow * DPAD;
        nc0 = DPAD / 64;  // 5
        Ar[1] = g_h0b[pp] + (size_t)(m0 + r) * H_DIM;
        Wr[1] = g_whh0 + (size_t)wrow * H_DIM;
    } else {
        Ar[0] = g_h0b[pp ^ 1] + (size_t)(m0 + r) * H_DIM;  // h0 of this step
        Wr[0] = g_wih1 + (size_t)wrow * H_DIM;
        nc0 = H_DIM / 64;  // 16
        Ar[1] = g_h1b[pp] + (size_t)(m0 + r) * H_DIM;
        Wr[1] = g_whh1 + (size_t)wrow * H_DIM;
    }
    const int NC = nc0 + H_DIM / 64;  // 21 or 32

    float acc[4][4][4];
#pragma unroll
    for (int mi = 0; mi < 4; mi++)
#pragma unroll
        for (int nf = 0; nf < 4; nf++)
#pragma unroll
            for (int q = 0; q < 4; q++) acc[mi][nf][q] = 0.0f;

    auto ldchunk = [&](int c, int buf) {
        const int sg = (c < nc0) ? 0 : 1;
        const int k0 = ((c < nc0) ? c : (c - nc0)) * 64;
        const __half* pa = Ar[sg];
        const __half* pw = Wr[sg];
        const u32 d = sb + (u32)buf * BUF_B;
#pragma unroll
        for (int j = 0; j < 4; j++) {
            const int q = h4 + j;
            const u32 so = swz((u32)r, (u32)q);
            const int e = k0 + q * 8;
            cp16(d + so, pa + e);
            cp16(d + TILE_B + so, pw + e);
        }
    };

    ldchunk(0, 0); CP_COMMIT();
    ldchunk(1, 1); CP_COMMIT();

    int buf = 0, nbuf = 2;  // buffer holding chunk c; buffer for chunk c+2
    for (int c = 0; c < NC; c++) {
        if (c + 1 < NC) { CP_WAIT1(); }
        else            { CP_WAIT0(); }
        __syncthreads();  // chunk c visible; all prior reads of nbuf finished
        if (c + 2 < NC) { ldchunk(c + 2, nbuf); CP_COMMIT(); }

        const u32 bA = sb + (u32)buf * BUF_B;
        const u32 bW = bA + TILE_B;

#pragma unroll
        for (int kk = 0; kk < 4; kk++) {
            u32 a[4][4], w[2][4];
            const u32 aq = 2 * kk + (lane >> 4);
#pragma unroll
            for (int mi = 0; mi < 4; mi++) {
                const u32 row = wm * 64 + mi * 16 + (lane & 15);
                ldsm4(bA + swz(row, aq), a[mi]);
            }
            const u32 wq = 2 * kk + ((lane >> 3) & 1);
#pragma unroll
            for (int nf2 = 0; nf2 < 2; nf2++) {
                const u32 row = wn * 32 + nf2 * 16 + (lane & 7) + ((lane >> 4) << 3);
                ldsm4(bW + swz(row, wq), w[nf2]);
            }
#pragma unroll
            for (int mi = 0; mi < 4; mi++)
#pragma unroll
                for (int nf = 0; nf < 4; nf++) {
                    const u32* W = w[nf >> 1] + (nf & 1) * 2;
                    mma_f16(acc[mi][nf], a[mi], W[0], W[1]);
                }
        }
        buf = (buf + 1 == N_STAGE) ? 0 : buf + 1;
        nbuf = (nbuf + 1 == N_STAGE) ? 0 : nbuf + 1;
    }

    // ---------------- fused LSTM epilogue ----------------
    float* cmem = layer ? g_c1 : g_c0;
    __half* hout = (layer ? g_h1b[pp ^ 1] : g_h0b[pp ^ 1]);
    const bool owner = ((lane & 1) == 0);
    const int cc = 2 * (lane & 3);

#pragma unroll
    for (int mi = 0; mi < 4; mi++)
#pragma unroll
        for (int nf = 0; nf < 4; nf++) {
            float v0 = acc[mi][nf][0], v1 = acc[mi][nf][1];
            float v2 = acc[mi][nf][2], v3 = acc[mi][nf][3];
            const float p0 = __shfl_xor_sync(0xffffffffu, v0, 1);
            const float p1 = __shfl_xor_sync(0xffffffffu, v1, 1);
            const float p2 = __shfl_xor_sync(0xffffffffu, v2, 1);
            const float p3 = __shfl_xor_sync(0xffffffffu, v3, 1);
            if (owner) {
                const int nl = wn * 32 + nf * 8 + cc;
                const int ucol = u0 + (nl >> 2);
                const float bi = sbias[nl], bf = sbias[nl + 1];
                const float bg = sbias[nl + 2], bo = sbias[nl + 3];
                const int rowa = m0 + wm * 64 + mi * 16 + (lane >> 2);
#pragma unroll
                for (int rh = 0; rh < 2; rh++) {
                    const int b = rowa + rh * 8;
                    const float iv = (rh ? v2 : v0) + bi;
                    const float fv = (rh ? v3 : v1) + bf;
                    const float gv = (rh ? p2 : p0) + bg;
                    const float ov = (rh ? p3 : p1) + bo;
                    const size_t ci = (size_t)b * H_DIM + ucol;
                    const float cold = cmem[ci];
                    const float cn = sigf(fv) * cold + sigf(iv) * tanhf_(gv);
                    const float hn = sigf(ov) * tanhf_(cn);
                    cmem[ci] = cn;
                    hout[ci] = __float2half(hn);
                    if (layer) g_acc[ci] += hn;
                }
            }
        }
}

// ------------------------------------------------------------------
// Single fused prologue: convert weights/x to fp16, zero states.
// ------------------------------------------------------------------
__global__ void prolog_k(const float* __restrict__ x,
                         const float* __restrict__ Wih0, const float* __restrict__ Whh0,
                         const float* __restrict__ Wih1, const float* __restrict__ Whh1) {
    const size_t stride = (size_t)gridDim.x * blockDim.x;
    const size_t tid0 = (size_t)blockIdx.x * blockDim.x + threadIdx.x;

    {
        const size_t n = (size_t)4 * H_DIM * DPAD;
        for (size_t i = tid0; i < n; i += stride) {
            const size_t row = i / DPAD;
            const int k = (int)(i % DPAD);
            g_wih0[i] = __float2half((k < D_DIM) ? Wih0[row * D_DIM + k] : 0.0f);
        }
    }
    {
        const size_t n = (size_t)4 * H_DIM * H_DIM;
        for (size_t i = tid0; i < n; i += stride) {
            g_whh0[i] = __float2half(Whh0[i]);
            g_wih1[i] = __float2half(Wih1[i]);
            g_whh1[i] = __float2half(Whh1[i]);
        }
    }
    {
        const size_t n = (size_t)B_DIM * T_DIM * DPAD;
        for (size_t i = tid0; i < n; i += stride) {
            const size_t bt = i / DPAD;
            const int k = (int)(i % DPAD);
            g_x[i] = __float2half((k < D_DIM) ? x[bt * D_DIM + k] : 0.0f);
        }
    }
    {
        const size_t n = (size_t)B_DIM * H_DIM;
        for (size_t i = tid0; i < n; i += stride) {
            g_h0b[0][i] = __float2half(0.0f);
            g_h1b[0][i] = __float2half(0.0f);
            g_c0[i] = 0.0f; g_c1[i] = 0.0f; g_acc[i] = 0.0f;
        }
    }
}

__global__ void finalize_k(const float* __restrict__ Wdec,
                           const float* __restrict__ bdec, float* __restrict__ out) {
    const int b = blockIdx.x;
    const int tid = threadIdx.x;  // 128
    float p = 0.0f;
    for (int u = tid; u < H_DIM; u += 128)
        p += g_acc[(size_t)b * H_DIM + u] * Wdec[u];
#pragma unroll
    for (int o = 16; o; o >>= 1) p += __shfl_down_sync(0xffffffffu, p, o);
    __shared__ float red[4];
    if ((tid & 31) == 0) red[tid >> 5] = p;
    __syncthreads();
    if (tid == 0)
        out[b] = (red[0] + red[1] + red[2] + red[3]) * (1.0f / (float)T_DIM) + bdec[0];
}

// ------------------------------------------------------------------
extern "C" void kernel_launch(void* const* d_in, const int* in_sizes, int n_in,
                              void* d_out, int out_size) {
    const float* x    = (const float*)d_in[0];
    const float* Wih0 = (const float*)d_in[1];
    const float* Whh0 = (const float*)d_in[2];
    const float* bih0 = (const float*)d_in[3];
    const float* bhh0 = (const float*)d_in[4];
    const float* Wih1 = (const float*)d_in[5];
    const float* Whh1 = (const float*)d_in[6];
    const float* bih1 = (const float*)d_in[7];
    const float* bhh1 = (const float*)d_in[8];
    const float* Wdec = (const float*)d_in[9];
    const float* bdec = (const float*)d_in[10];
    float* out = (float*)d_out;

    cudaFuncSetAttribute(lstm_step, cudaFuncAttributeMaxDynamicSharedMemorySize, SMEM_TOT);

    prolog_k<<<2048, 256>>>(x, Wih0, Whh0, Wih1, Whh1);

    // step 0 layer0 alone
    lstm_step<<<128, 256, SMEM_TOT>>>(0, 0, bih0, bhh0, bih1, bhh1);
    // merged intervals: layer1[t] || layer0[t+1]
    for (int t = 0; t < T_DIM - 1; ++t)
        lstm_step<<<256, 256, SMEM_TOT>>>(1, t, bih0, bhh0, bih1, bhh1);
    // final layer1
    lstm_step<<<128, 256, SMEM_TOT>>>(2, T_DIM - 1, bih0, bhh0, bih1, bhh1);

    finalize_k<<<B_DIM, 128>>>(Wdec, bdec, out);
}

// round 8
// speedup vs baseline: 1.5871x; 1.0770x over previous
#include <cuda_runtime.h>
#include <cuda_fp16.h>
#include <cstdint>

#define B_DIM 512
#define T_DIM 128
#define D_DIM 300
#define DPAD  320
#define H_DIM 1024
#define NCOL  4096   // 4*H

typedef uint32_t u32;

// ------------------------------------------------------------------
// Persistent device buffers
// ------------------------------------------------------------------
__device__ __align__(16) __half g_x[(size_t)B_DIM * T_DIM * DPAD];
__device__ __align__(16) __half g_wih0[(size_t)4 * H_DIM * DPAD];
__device__ __align__(16) __half g_whh0[(size_t)4 * H_DIM * H_DIM];
__device__ __align__(16) __half g_wih1[(size_t)4 * H_DIM * H_DIM];
__device__ __align__(16) __half g_whh1[(size_t)4 * H_DIM * H_DIM];
__device__ __align__(16) __half g_h0b[2][(size_t)B_DIM * H_DIM];
__device__ __align__(16) __half g_h1b[2][(size_t)B_DIM * H_DIM];
__device__ __align__(16) float g_part[2][(size_t)B_DIM * NCOL];  // L1 partial gates
__device__ __align__(16) float g_c0[(size_t)B_DIM * H_DIM];
__device__ __align__(16) float g_c1[(size_t)B_DIM * H_DIM];
__device__ __align__(16) float g_acc[(size_t)B_DIM * H_DIM];

// ------------------------------------------------------------------
// Helpers
// ------------------------------------------------------------------
__device__ __forceinline__ u32 smem_to_u32(const void* p) {
    u32 a;
    asm("{ .reg .u64 t; cvta.to.shared.u64 t, %1; cvt.u32.u64 %0, t; }" : "=r"(a) : "l"(p));
    return a;
}
__device__ __forceinline__ void cp16(u32 s, const void* g) {
    asm volatile("cp.async.cg.shared.global [%0], [%1], 16;" :: "r"(s), "l"(g));
}
__device__ __forceinline__ void mbar_init(u32 mb, u32 cnt) {
    asm volatile("mbarrier.init.shared.b64 [%0], %1;" :: "r"(mb), "r"(cnt) : "memory");
}
__device__ __forceinline__ void mbar_arrive(u32 mb) {
    asm volatile("mbarrier.arrive.shared.b64 _, [%0];" :: "r"(mb) : "memory");
}
__device__ __forceinline__ void cp_arrive_noinc(u32 mb) {
    asm volatile("cp.async.mbarrier.arrive.noinc.shared.b64 [%0];" :: "r"(mb) : "memory");
}
__device__ __forceinline__ void mbar_wait(u32 mb, u32 parity) {
    u32 done;
    asm volatile("{\n\t.reg .pred p;\n\t"
        "mbarrier.try_wait.parity.acquire.cta.shared::cta.b64 p, [%1], %2;\n\t"
        "selp.b32 %0, 1, 0, p;\n\t}" : "=r"(done) : "r"(mb), "r"(parity) : "memory");
    if (!done) {
        asm volatile("{\n\t.reg .pred P1;\n\t"
            "WAIT_LOOP_%=:\n\t"
            "mbarrier.try_wait.parity.acquire.cta.shared::cta.b64 P1, [%0], %1, 0x989680;\n\t"
            "@P1 bra.uni WAIT_DONE_%=;\n\t"
            "bra.uni WAIT_LOOP_%=;\n\t"
            "WAIT_DONE_%=:\n\t}" :: "r"(mb), "r"(parity) : "memory");
    }
}
__device__ __forceinline__ void ldsm4(u32 addr, u32* r) {
    asm volatile("ldmatrix.sync.aligned.m8n8.x4.shared.b16 {%0,%1,%2,%3}, [%4];"
                 : "=r"(r[0]), "=r"(r[1]), "=r"(r[2]), "=r"(r[3]) : "r"(addr));
}
__device__ __forceinline__ void mma_f16(float* d, const u32* a, u32 b0, u32 b1) {
    asm volatile("mma.sync.aligned.m16n8k16.row.col.f32.f16.f16.f32 "
                 "{%0,%1,%2,%3}, {%4,%5,%6,%7}, {%8,%9}, {%0,%1,%2,%3};"
                 : "+f"(d[0]), "+f"(d[1]), "+f"(d[2]), "+f"(d[3])
                 : "r"(a[0]), "r"(a[1]), "r"(a[2]), "r"(a[3]), "r"(b0), "r"(b1));
}
__device__ __forceinline__ u32 swz(u32 row, u32 q) {
    return row * 128u + ((q ^ (row & 7u)) << 4);
}
__device__ __forceinline__ float sigf(float x) { return __fdividef(1.0f, 1.0f + __expf(-x)); }
__device__ __forceinline__ float tanhf_(float x) {
    return 1.0f - 2.0f * __fdividef(1.0f, 1.0f + __expf(2.0f * x));
}

#define TILE_B   16384          // 128 x 64 fp16
#define BUF_B    (2 * TILE_B)   // A, W
#define SMEM_TOT (1024 + 3 * BUF_B)  // 99328 -> 2 CTAs/SM

// ------------------------------------------------------------------
// Job types: 0 = L1B (h1@Whh1 + partial -> cell1), 1 = L1A (h0@Wih1 ->
// partial raw store), 2 = L0 (x@Wih0 + h0@Whh0 -> cell0).
// CTA: 256 thr, 8 warps (2Mx4N), tile 128x128, warp 64x32, BK=64.
// mbarrier 3-stage producer/consumer ring, NO per-chunk __syncthreads.
// ------------------------------------------------------------------
__global__ void __launch_bounds__(256, 2)
lstm_step(int s_l0, int s_l1b, int s_l1a,
          const float* __restrict__ bih0, const float* __restrict__ bhh0,
          const float* __restrict__ bih1, const float* __restrict__ bhh1) {
    extern __shared__ __align__(16) char smem[];
    const u32 sbase = smem_to_u32(smem);
    const u32 sbm = sbase + 32;         // full[0..2] @ +0,8,16 ; empty[0..2] @ +24,32,40
    const u32 sb = sbase + 1024;        // tile stages
    float* sbias = (float*)(smem + 128);
    const int tid = threadIdx.x;
    const int lane = tid & 31;
    const int wid = tid >> 5;
    const int wm = wid >> 2;
    const int wn = wid & 3;

    // job decode (ordered L0, L1B, L1A; longest first for wave-1 priority)
    const int g = blockIdx.x >> 7;
    const int jb = blockIdx.x & 127;
    int type = 2, step = 0;
    {
        int k = 0;
        if (s_l0 >= 0)  { if (g == k) { type = 2; step = s_l0; }  k++; }
        if (s_l1b >= 0) { if (g == k) { type = 0; step = s_l1b; } k++; }
        if (s_l1a >= 0) { if (g == k) { type = 1; step = s_l1a; } k++; }
    }
    const int u0 = (jb & 31) * 32;
    const int m0 = (jb >> 5) * 128;

    if (tid == 0) {
#pragma unroll
        for (int s = 0; s < 3; s++) {
            mbar_init(sbm + s * 8, 256);       // full[s]
            mbar_init(sbm + 24 + s * 8, 256);  // empty[s]
        }
    }
    if (type != 1 && tid < 128) {
        const float* bih = (type == 0) ? bih1 : bih0;
        const float* bhh = (type == 0) ? bhh1 : bhh0;
        const int wr = (tid & 3) * H_DIM + u0 + (tid >> 2);
        sbias[tid] = bih[wr] + bhh[wr];
    }
    __syncthreads();  // mbarrier init + sbias visible

    // per-thread load row
    const int r = tid >> 1;
    const int h4 = (tid & 1) * 4;
    const int wrow = (r & 3) * H_DIM + u0 + (r >> 2);

    const __half *pa0, *pw0, *pa1 = nullptr, *pw1 = nullptr;
    int nc0, NC;
    if (type == 2) {           // L0
        pa0 = g_x + (size_t)(m0 + r) * (T_DIM * DPAD) + (size_t)step * DPAD;
        pw0 = g_wih0 + (size_t)wrow * DPAD;
        nc0 = DPAD / 64;  // 5
        pa1 = g_h0b[(step - 1) & 1] + (size_t)(m0 + r) * H_DIM;  // h0[t-1]; t=0 -> buf1 (zeroed)
        pw1 = g_whh0 + (size_t)wrow * H_DIM;
        NC = nc0 + 16;    // 21
    } else if (type == 1) {    // L1A
        pa0 = g_h0b[step & 1] + (size_t)(m0 + r) * H_DIM;
        pw0 = g_wih1 + (size_t)wrow * H_DIM;
        nc0 = 16; NC = 16;
    } else {                   // L1B
        pa0 = g_h1b[(step - 1) & 1] + (size_t)(m0 + r) * H_DIM;  // h1[t-1]; t=0 -> buf1 (zeroed)
        pw0 = g_whh1 + (size_t)wrow * H_DIM;
        nc0 = 16; NC = 16;
    }

    float acc[4][4][4];
#pragma unroll
    for (int mi = 0; mi < 4; mi++)
#pragma unroll
        for (int nf = 0; nf < 4; nf++)
#pragma unroll
            for (int q = 0; q < 4; q++) acc[mi][nf][q] = 0.0f;

    auto produce = [&](int c) {
        const __half* pa; const __half* pw; int k0;
        if (c < nc0) { pa = pa0; pw = pw0; k0 = c * 64; }
        else         { pa = pa1; pw = pw1; k0 = (c - nc0) * 64; }
        const u32 d = sb + (u32)(c % 3) * BUF_B;
#pragma unroll
        for (int j = 0; j < 4; j++) {
            const int q = h4 + j;
            const u32 so = swz((u32)r, (u32)q);
            const int e = k0 + q * 8;
            cp16(d + so, pa + e);
            cp16(d + TILE_B + so, pw + e);
        }
        cp_arrive_noinc(sbm + (u32)(c % 3) * 8);  // async arrive on full[c%3]
    };

    produce(0);
    produce(1);

    for (int c = 0; c < NC; c++) {
        const int pc = c + 2;
        if (pc < NC) {
            if (pc >= 3)  // wait empty[pc%3] phase (pc/3 - 1)
                mbar_wait(sbm + 24 + (u32)(pc % 3) * 8, (u32)(((pc / 3) - 1) & 1));
            produce(pc);
        }
        // wait full[c%3] phase (c/3)
        mbar_wait(sbm + (u32)(c % 3) * 8, (u32)((c / 3) & 1));

        const u32 bA = sb + (u32)(c % 3) * BUF_B;
        const u32 bW = bA + TILE_B;
#pragma unroll
        for (int kk = 0; kk < 4; kk++) {
            u32 a[4][4], w[2][4];
            const u32 aq = 2 * kk + (lane >> 4);
#pragma unroll
            for (int mi = 0; mi < 4; mi++) {
                const u32 row = wm * 64 + mi * 16 + (lane & 15);
                ldsm4(bA + swz(row, aq), a[mi]);
            }
            const u32 wq = 2 * kk + ((lane >> 3) & 1);
#pragma unroll
            for (int nf2 = 0; nf2 < 2; nf2++) {
                const u32 row = wn * 32 + nf2 * 16 + (lane & 7) + ((lane >> 4) << 3);
                ldsm4(bW + swz(row, wq), w[nf2]);
            }
#pragma unroll
            for (int mi = 0; mi < 4; mi++)
#pragma unroll
                for (int nf = 0; nf < 4; nf++) {
                    const u32* W = w[nf >> 1] + (nf & 1) * 2;
                    mma_f16(acc[mi][nf], a[mi], W[0], W[1]);
                }
        }
        mbar_arrive(sbm + 24 + (u32)(c % 3) * 8);  // empty[c%3]
    }

    // ---------------- epilogues ----------------
    if (type == 1) {  // raw partial store
        float* outp = g_part[step & 1];
#pragma unroll
        for (int mi = 0; mi < 4; mi++)
#pragma unroll
            for (int nf = 0; nf < 4; nf++) {
                const int row0 = m0 + wm * 64 + mi * 16 + (lane >> 2);
                const int col = u0 * 4 + wn * 32 + nf * 8 + 2 * (lane & 3);
                *(float2*)(outp + (size_t)row0 * NCOL + col) =
                    make_float2(acc[mi][nf][0], acc[mi][nf][1]);
                *(float2*)(outp + (size_t)(row0 + 8) * NCOL + col) =
                    make_float2(acc[mi][nf][2], acc[mi][nf][3]);
            }
        return;
    }

    float* cmem;
    __half* hout;
    const float* extra;
    if (type == 0) { cmem = g_c1; hout = g_h1b[step & 1]; extra = g_part[step & 1]; }
    else           { cmem = g_c0; hout = g_h0b[step & 1]; extra = nullptr; }
    const bool owner = ((lane & 1) == 0);
    const int cc = 2 * (lane & 3);

#pragma unroll
    for (int mi = 0; mi < 4; mi++)
#pragma unroll
        for (int nf = 0; nf < 4; nf++) {
            float v0 = acc[mi][nf][0], v1 = acc[mi][nf][1];
            float v2 = acc[mi][nf][2], v3 = acc[mi][nf][3];
            const float p0 = __shfl_xor_sync(0xffffffffu, v0, 1);
            const float p1 = __shfl_xor_sync(0xffffffffu, v1, 1);
            const float p2 = __shfl_xor_sync(0xffffffffu, v2, 1);
            const float p3 = __shfl_xor_sync(0xffffffffu, v3, 1);
            if (owner) {
                const int nl = wn * 32 + nf * 8 + cc;
                const int ucol = u0 + (nl >> 2);
                const float bi = sbias[nl], bf = sbias[nl + 1];
                const float bg = sbias[nl + 2], bo = sbias[nl + 3];
                const int rowa = m0 + wm * 64 + mi * 16 + (lane >> 2);
#pragma unroll
                for (int rh = 0; rh < 2; rh++) {
                    const int b = rowa + rh * 8;
                    float iv = (rh ? v2 : v0) + bi;
                    float fv = (rh ? v3 : v1) + bf;
                    float gv = (rh ? p2 : p0) + bg;
                    float ov = (rh ? p3 : p1) + bo;
                    if (extra) {
                        const float2 e01 = *(const float2*)(extra + (size_t)b * NCOL + u0 * 4 + nl);
                        const float2 e23 = *(const float2*)(extra + (size_t)b * NCOL + u0 * 4 + nl + 2);
                        iv += e01.x; fv += e01.y; gv += e23.x; ov += e23.y;
                    }
                    const size_t ci = (size_t)b * H_DIM + ucol;
                    const float cold = cmem[ci];
                    const float cn = sigf(fv) * cold + sigf(iv) * tanhf_(gv);
                    const float hn = sigf(ov) * tanhf_(cn);
                    cmem[ci] = cn;
                    hout[ci] = __float2half(hn);
                    if (type == 0) g_acc[ci] += hn;
                }
            }
        }
}

// ------------------------------------------------------------------
__global__ void prolog_k(const float* __restrict__ x,
                         const float* __restrict__ Wih0, const float* __restrict__ Whh0,
                         const float* __restrict__ Wih1, const float* __restrict__ Whh1) {
    const size_t stride = (size_t)gridDim.x * blockDim.x;
    const size_t tid0 = (size_t)blockIdx.x * blockDim.x + threadIdx.x;
    {
        const size_t n = (size_t)4 * H_DIM * DPAD;
        for (size_t i = tid0; i < n; i += stride) {
            const size_t row = i / DPAD;
            const int k = (int)(i % DPAD);
            g_wih0[i] = __float2half((k < D_DIM) ? Wih0[row * D_DIM + k] : 0.0f);
        }
    }
    {
        const size_t n = (size_t)4 * H_DIM * H_DIM;
        for (size_t i = tid0; i < n; i += stride) {
            g_whh0[i] = __float2half(Whh0[i]);
            g_wih1[i] = __float2half(Wih1[i]);
            g_whh1[i] = __float2half(Whh1[i]);
        }
    }
    {
        const size_t n = (size_t)B_DIM * T_DIM * DPAD;
        for (size_t i = tid0; i < n; i += stride) {
            const size_t bt = i / DPAD;
            const int k = (int)(i % DPAD);
            g_x[i] = __float2half((k < D_DIM) ? x[bt * D_DIM + k] : 0.0f);
        }
    }
    {
        const size_t n = (size_t)B_DIM * H_DIM;
        for (size_t i = tid0; i < n; i += stride) {
            g_h0b[0][i] = __float2half(0.0f);
            g_h0b[1][i] = __float2half(0.0f);
            g_h1b[0][i] = __float2half(0.0f);
            g_h1b[1][i] = __float2half(0.0f);
            g_c0[i] = 0.0f; g_c1[i] = 0.0f; g_acc[i] = 0.0f;
        }
    }
}

__global__ void finalize_k(const float* __restrict__ Wdec,
                           const float* __restrict__ bdec, float* __restrict__ out) {
    const int b = blockIdx.x;
    const int tid = threadIdx.x;  // 128
    float p = 0.0f;
    for (int u = tid; u < H_DIM; u += 128)
        p += g_acc[(size_t)b * H_DIM + u] * Wdec[u];
#pragma unroll
    for (int o = 16; o; o >>= 1) p += __shfl_down_sync(0xffffffffu, p, o);
    __shared__ float red[4];
    if ((tid & 31) == 0) red[tid >> 5] = p;
    __syncthreads();
    if (tid == 0)
        out[b] = (red[0] + red[1] + red[2] + red[3]) * (1.0f / (float)T_DIM) + bdec[0];
}

// ------------------------------------------------------------------
extern "C" void kernel_launch(void* const* d_in, const int* in_sizes, int n_in,
                              void* d_out, int out_size) {
    const float* x    = (const float*)d_in[0];
    const float* Wih0 = (const float*)d_in[1];
    const float* Whh0 = (const float*)d_in[2];
    const float* bih0 = (const float*)d_in[3];
    const float* bhh0 = (const float*)d_in[4];
    const float* Wih1 = (const float*)d_in[5];
    const float* Whh1 = (const float*)d_in[6];
    const float* bih1 = (const float*)d_in[7];
    const float* bhh1 = (const float*)d_in[8];
    const float* Wdec = (const float*)d_in[9];
    const float* bdec = (const float*)d_in[10];
    float* out = (float*)d_out;

    cudaFuncSetAttribute(lstm_step, cudaFuncAttributeMaxDynamicSharedMemorySize, SMEM_TOT);

    prolog_k<<<2048, 256>>>(x, Wih0, Whh0, Wih1, Whh1);

    // schedule: launch(t) = { L0[t+1], L1B[t-1], L1A[t] }
    lstm_step<<<128, 256, SMEM_TOT>>>(0, -1, -1, bih0, bhh0, bih1, bhh1);   // L0[0]
    lstm_step<<<256, 256, SMEM_TOT>>>(1, -1, 0, bih0, bhh0, bih1, bhh1);    // L0[1], L1A[0]
    for (int t = 1; t <= T_DIM - 2; ++t)                                    // t = 1..126
        lstm_step<<<384, 256, SMEM_TOT>>>(t + 1, t - 1, t, bih0, bhh0, bih1, bhh1);
    lstm_step<<<256, 256, SMEM_TOT>>>(-1, T_DIM - 2, T_DIM - 1, bih0, bhh0, bih1, bhh1);
    lstm_step<<<128, 256, SMEM_TOT>>>(-1, T_DIM - 1, -1, bih0, bhh0, bih1, bhh1);

    finalize_k<<<B_DIM, 128>>>(Wdec, bdec, out);
}